// round 2
// baseline (speedup 1.0000x reference)
#include <cuda_runtime.h>
#include <cstdint>

// ---------------------------------------------------------------------------
// Gazs cell via legacy tensor-core path (baseline PTX only — the harness
// assembles for plain sm_103, so tcgen05/'a'-features are unavailable).
//
// GEMM: A=[h|x|glo] (M=8192,K=4096) x W^T rows, tf32 mma.sync.m16n8k8.
// CTA tile: 128 rows x 64 gate-cols x 3 gates (N=192). Gates interleaved at
// n8 granularity in SMEM so each thread owns (i,f,c) triples in registers;
// epilogue blends with h in-register, gates never touch GMEM.
// ---------------------------------------------------------------------------

#define BM 128
#define BNG 64                  // gate columns per CTA
#define BN 192                  // 3 * BNG rows in B tile
#define KC 16                   // K elements per stage
#define NSTAGES 6
#define A_STRIDE 20             // floats per SMEM row (16 data + 4 pad) -> conflict-free
#define A_TILE_BYTES (BM * A_STRIDE * 4)     // 10240
#define B_TILE_BYTES (BN * A_STRIDE * 4)     // 15360
#define STAGE_BYTES  (A_TILE_BYTES + B_TILE_BYTES)  // 25600
#define DYN_SMEM     (NSTAGES * STAGE_BYTES)        // 153600

__device__ __forceinline__ uint32_t smem_u32(const void* p) {
    uint32_t a;
    asm("{ .reg .u64 t; cvta.to.shared.u64 t, %1; cvt.u32.u64 %0, t; }" : "=r"(a) : "l"(p));
    return a;
}
__device__ __forceinline__ void cp16(uint32_t dst, const void* src) {
    asm volatile("cp.async.cg.shared.global [%0], [%1], 16;" :: "r"(dst), "l"(src));
}
__device__ __forceinline__ void cp_commit() {
    asm volatile("cp.async.commit_group;" ::: "memory");
}
__device__ __forceinline__ void wait_groups(int w) {
    switch (w) {
        case 0: asm volatile("cp.async.wait_group 0;" ::: "memory"); break;
        case 1: asm volatile("cp.async.wait_group 1;" ::: "memory"); break;
        case 2: asm volatile("cp.async.wait_group 2;" ::: "memory"); break;
        case 3: asm volatile("cp.async.wait_group 3;" ::: "memory"); break;
        default: asm volatile("cp.async.wait_group 4;" ::: "memory"); break;
    }
}
__device__ __forceinline__ uint32_t to_tf32(float v) {
    uint32_t r;
    asm("cvt.rna.tf32.f32 %0, %1;" : "=r"(r) : "f"(v));
    return r;
}
__device__ __forceinline__ void mma_tf32(float d[4], const uint32_t a[4], const uint32_t b[2]) {
    asm volatile(
        "mma.sync.aligned.m16n8k8.row.col.f32.tf32.tf32.f32 "
        "{%0,%1,%2,%3}, {%4,%5,%6,%7}, {%8,%9}, {%0,%1,%2,%3};"
        : "+f"(d[0]), "+f"(d[1]), "+f"(d[2]), "+f"(d[3])
        : "r"(a[0]), "r"(a[1]), "r"(a[2]), "r"(a[3]), "r"(b[0]), "r"(b[1]));
}
__device__ __forceinline__ float fast_sigmoid(float v) {
    return __fdividef(1.f, 1.f + __expf(-v));
}
__device__ __forceinline__ float fast_tanh(float v) {
    // 1 - 2/(exp(2v)+1); saturation-safe at both ends with __expf
    return 1.f - __fdividef(2.f, __expf(2.f * v) + 1.f);
}

// Issue one stage's loads: A tile 128x16 fp32 + B tile 192x16 fp32.
// B rows interleave gates at n8 granularity: row j = b*24 + g*8 + w
// (b = n8 block 0..7, g = gate 0..2, w = col-in-block 0..7).
__device__ __forceinline__ void issue_stage(
    uint32_t sbase, int tid, int kc, int m0, int n0, int H, int K,
    const float* __restrict__ h, const float* __restrict__ x, const float* __restrict__ glo,
    const float* __restrict__ Wi, const float* __restrict__ Wf, const float* __restrict__ Wc)
{
    const int k0 = kc * KC;
    const float* ab; int astr, ac;
    if (k0 < H)          { ab = h;   astr = H;     ac = k0; }
    else if (k0 < 3 * H) { ab = x;   astr = 2 * H; ac = k0 - H; }
    else                 { ab = glo; astr = H;     ac = k0 - 3 * H; }

#pragma unroll
    for (int jj = 0; jj < 5; jj++) {
        int idx = tid + (jj << 8);
        if (idx < 512) {                       // A: 128 rows * 4 x 16B
            int row = idx >> 2, s = idx & 3;
            const float* src = ab + (size_t)(m0 + row) * astr + ac + s * 4;
            cp16(sbase + (uint32_t)row * (A_STRIDE * 4) + (uint32_t)s * 16u, src);
        } else {                               // B: 192 rows * 4 x 16B
            int t = idx - 512;
            int row = t >> 2, s = t & 3;
            int b = row / 24;
            int rem = row - b * 24;
            int g = rem >> 3, w = rem & 7;
            const float* wp = (g == 0) ? Wi : (g == 1) ? Wf : Wc;
            const float* src = wp + (size_t)(n0 + b * 8 + w) * K + k0 + s * 4;
            cp16(sbase + A_TILE_BYTES + (uint32_t)row * (A_STRIDE * 4) + (uint32_t)s * 16u, src);
        }
    }
    cp_commit();
}

__global__ void __launch_bounds__(256, 1) gazs_cell_kernel(
    const float* __restrict__ h, const float* __restrict__ x, const float* __restrict__ glo,
    const float* __restrict__ Wi, const float* __restrict__ Wib,
    const float* __restrict__ Wf, const float* __restrict__ Wfb,
    const float* __restrict__ Wc, const float* __restrict__ Wcb,
    float* __restrict__ out, int H)
{
    extern __shared__ __align__(128) char smem[];
    const uint32_t sb = smem_u32(smem);

    const int K  = 4 * H;
    const int NC = K / KC;                 // 256
    const int tid  = threadIdx.x;
    const int lane = tid & 31;
    const int wid  = tid >> 5;
    const int wm   = wid & 3;              // 4 warps down M (32 rows each)
    const int wn   = wid >> 2;             // 2 warps across N (96 cols each)
    const int m0   = blockIdx.y * BM;
    const int n0   = blockIdx.x * BNG;
    const int qr   = lane >> 2;            // 0..7
    const int qc   = lane & 3;             // 0..3

    float acc[2][12][4];
#pragma unroll
    for (int mt = 0; mt < 2; mt++)
#pragma unroll
        for (int nt = 0; nt < 12; nt++)
#pragma unroll
            for (int c = 0; c < 4; c++) acc[mt][nt][c] = 0.f;

    // ---- prologue: prime NSTAGES-1 stages ---------------------------------
#pragma unroll
    for (int s = 0; s < NSTAGES - 1; s++)
        issue_stage(sb + (uint32_t)s * STAGE_BYTES, tid, s, m0, n0, H, K, h, x, glo, Wi, Wf, Wc);

    const float* As_base = (const float*)smem;

    for (int kc = 0; kc < NC; kc++) {
        int w = NC - 1 - kc; if (w > NSTAGES - 2) w = NSTAGES - 2;
        wait_groups(w);
        __syncthreads();

        int pf = kc + NSTAGES - 1;
        if (pf < NC) {
            int ps = pf % NSTAGES;
            issue_stage(sb + (uint32_t)ps * STAGE_BYTES, tid, pf, m0, n0, H, K, h, x, glo, Wi, Wf, Wc);
        }

        const float* As = As_base + (size_t)(kc % NSTAGES) * (STAGE_BYTES / 4);
        const float* Bs = As + (A_TILE_BYTES / 4);

#pragma unroll
        for (int k8 = 0; k8 < 2; k8++) {
            const int kb = k8 * 8 + qc;
            uint32_t af[2][4], bf[12][2];
#pragma unroll
            for (int mt = 0; mt < 2; mt++) {
                int r = wm * 32 + mt * 16 + qr;
                af[mt][0] = to_tf32(As[r * A_STRIDE + kb]);
                af[mt][1] = to_tf32(As[(r + 8) * A_STRIDE + kb]);
                af[mt][2] = to_tf32(As[r * A_STRIDE + kb + 4]);
                af[mt][3] = to_tf32(As[(r + 8) * A_STRIDE + kb + 4]);
            }
#pragma unroll
            for (int nt = 0; nt < 12; nt++) {
                int n = wn * 96 + nt * 8 + qr;
                bf[nt][0] = to_tf32(Bs[n * A_STRIDE + kb]);
                bf[nt][1] = to_tf32(Bs[n * A_STRIDE + kb + 4]);
            }
#pragma unroll
            for (int mt = 0; mt < 2; mt++)
#pragma unroll
                for (int nt = 0; nt < 12; nt++)
                    mma_tf32(acc[mt][nt], af[mt], bf[nt]);
        }
    }

    // ---- epilogue: in-register gate blend, direct GMEM h read / out write --
    // acc[mt][b*3 + g] holds gate g for column pair n..n+1,
    // n = n0 + (wn*4+b)*8 + qc*2 ; rows = m0 + wm*32 + mt*16 + qr (+8).
#pragma unroll
    for (int mt = 0; mt < 2; mt++) {
        const int rbase = m0 + wm * 32 + mt * 16 + qr;
#pragma unroll
        for (int b = 0; b < 4; b++) {
            const int n = n0 + (wn * 4 + b) * 8 + qc * 2;
            const float bi0 = __ldg(Wib + n), bi1 = __ldg(Wib + n + 1);
            const float bff0 = __ldg(Wfb + n), bff1 = __ldg(Wfb + n + 1);
            const float bc0 = __ldg(Wcb + n), bc1 = __ldg(Wcb + n + 1);
            const float* ai = acc[mt][b * 3 + 0];
            const float* af_ = acc[mt][b * 3 + 1];
            const float* ac_ = acc[mt][b * 3 + 2];
#pragma unroll
            for (int rsel = 0; rsel < 2; rsel++) {
                const int row = rbase + rsel * 8;
                const int i0 = rsel * 2;
                float2 hv = *(const float2*)(h + (size_t)row * H + n);

                float iv0 = ai[i0] + bi0,      iv1 = ai[i0 + 1] + bi1;
                float fv0 = af_[i0] + bff0,    fv1 = af_[i0 + 1] + bff1;
                float cv0 = ac_[i0] + bc0,     cv1 = ac_[i0 + 1] + bc1;

                float ig0 = fast_sigmoid(iv0), ig1 = fast_sigmoid(iv1);
                float fg0 = fast_sigmoid(fv0), fg1 = fast_sigmoid(fv1);
                float cg0 = fast_tanh(cv0),    cg1 = fast_tanh(cv1);
                float al0 = fast_sigmoid(ig0 - fg0);
                float al1 = fast_sigmoid(ig1 - fg1);

                float2 ov;
                ov.x = fmaf(al0, cg0 - hv.x, hv.x);
                ov.y = fmaf(al1, cg1 - hv.y, hv.y);
                *(float2*)(out + (size_t)row * H + n) = ov;
            }
        }
    }
}

extern "C" void kernel_launch(void* const* d_in, const int* in_sizes, int n_in,
                              void* d_out, int out_size)
{
    const float* h   = (const float*)d_in[0];
    const float* x   = (const float*)d_in[1];
    const float* glo = (const float*)d_in[2];
    const float* Wi  = (const float*)d_in[3];
    const float* Wib = (const float*)d_in[4];
    const float* Wf  = (const float*)d_in[5];
    const float* Wfb = (const float*)d_in[6];
    const float* Wc  = (const float*)d_in[7];
    const float* Wcb = (const float*)d_in[8];
    float* out = (float*)d_out;

    const int H = in_sizes[4];             // bias length = 1024
    const int B = in_sizes[0] / H;         // 8192

    static int configured = 0;
    if (!configured) {
        cudaFuncSetAttribute(gazs_cell_kernel,
                             cudaFuncAttributeMaxDynamicSharedMemorySize, DYN_SMEM);
        configured = 1;
    }

    dim3 grid(H / BNG, B / BM);            // (16, 64) = 1024 CTAs
    gazs_cell_kernel<<<grid, 256, DYN_SMEM>>>(h, x, glo, Wi, Wib, Wf, Wfb, Wc, Wcb, out, H);
}

// round 3
// speedup vs baseline: 2.4549x; 2.4549x over previous
#include <cuda_runtime.h>
#include <cuda_fp16.h>
#include <cstdint>

// ---------------------------------------------------------------------------
// Gazs cell, legacy tensor-core path, fp16 inputs / fp32 accumulate.
// Phase 1: convert A=[h|x|glo] and gate-interleaved W to fp16 scratch.
// Phase 2: GEMM gates = A @ W^T with mma.sync.m16n8k16.f16 + fused epilogue.
// fp16 mantissa == tf32 mantissa (10 bits) -> same accuracy, 2x FLOP/instr.
// ---------------------------------------------------------------------------

#define BM 128
#define BN_GATE 128
#define BN 384                     // 3 gates * 128 cols
#define KC 32                      // fp16 k-elements per stage (64B/row)
#define NSTAGES 4
#define ROW_BYTES 80               // 64B data + 16B pad: conflict-free ldmatrix
#define A_TILE (BM * ROW_BYTES)            // 10240
#define B_TILE (BN * ROW_BYTES)            // 30720
#define STAGE  (A_TILE + B_TILE)           // 40960
#define DYN_SMEM (NSTAGES * STAGE)         // 163840

#define BATCH 8192
#define HDIM  1024
#define KDIM  4096

__device__ __align__(16) __half A16[(size_t)BATCH * KDIM];
__device__ __align__(16) __half W16[(size_t)3 * HDIM * KDIM];

// ---- helpers ---------------------------------------------------------------
__device__ __forceinline__ uint32_t smem_u32(const void* p) {
    uint32_t a;
    asm("{ .reg .u64 t; cvta.to.shared.u64 t, %1; cvt.u32.u64 %0, t; }" : "=r"(a) : "l"(p));
    return a;
}
__device__ __forceinline__ void cp16(uint32_t dst, const void* src) {
    asm volatile("cp.async.cg.shared.global [%0], [%1], 16;" :: "r"(dst), "l"(src));
}
__device__ __forceinline__ void cp_commit() {
    asm volatile("cp.async.commit_group;" ::: "memory");
}
__device__ __forceinline__ void wait_groups(int w) {
    if (w == 0)      asm volatile("cp.async.wait_group 0;" ::: "memory");
    else if (w == 1) asm volatile("cp.async.wait_group 1;" ::: "memory");
    else             asm volatile("cp.async.wait_group 2;" ::: "memory");
}
__device__ __forceinline__ void ldm_x4(uint32_t r[4], uint32_t addr) {
    asm volatile("ldmatrix.sync.aligned.m8n8.x4.shared.b16 {%0,%1,%2,%3}, [%4];"
        : "=r"(r[0]), "=r"(r[1]), "=r"(r[2]), "=r"(r[3]) : "r"(addr));
}
__device__ __forceinline__ void mma_f16(float d[4], const uint32_t a[4],
                                        uint32_t b0, uint32_t b1) {
    asm volatile(
        "mma.sync.aligned.m16n8k16.row.col.f32.f16.f16.f32 "
        "{%0,%1,%2,%3},{%4,%5,%6,%7},{%8,%9},{%0,%1,%2,%3};"
        : "+f"(d[0]), "+f"(d[1]), "+f"(d[2]), "+f"(d[3])
        : "r"(a[0]), "r"(a[1]), "r"(a[2]), "r"(a[3]), "r"(b0), "r"(b1));
}
__device__ __forceinline__ float fast_sigmoid(float v) {
    return __fdividef(1.f, 1.f + __expf(-v));
}
__device__ __forceinline__ float fast_tanh(float v) {
    return 1.f - __fdividef(2.f, __expf(2.f * v) + 1.f);
}

// ---- phase 1: converters ----------------------------------------------------
__global__ void conv_a_kernel(const float* __restrict__ h, const float* __restrict__ x,
                              const float* __restrict__ glo)
{
    const int m = blockIdx.x;
    __half* dst = A16 + (size_t)m * KDIM;
    const float* h_r = h + (size_t)m * HDIM;
    const float* x_r = x + (size_t)m * 2 * HDIM;
    const float* g_r = glo + (size_t)m * HDIM;
#pragma unroll 1
    for (int f4 = threadIdx.x; f4 < KDIM / 4; f4 += 256) {
        int k = f4 * 4;
        const float* src = (k < HDIM) ? (h_r + k)
                         : (k < 3 * HDIM) ? (x_r + (k - HDIM))
                         : (g_r + (k - 3 * HDIM));
        float4 v = *(const float4*)src;
        __half2 p0 = __floats2half2_rn(v.x, v.y);
        __half2 p1 = __floats2half2_rn(v.z, v.w);
        uint2 u;
        u.x = *(const uint32_t*)&p0;
        u.y = *(const uint32_t*)&p1;
        *(uint2*)(dst + k) = u;
    }
}

// W16 row j, j = b*24 + g*8 + w  (b = n8 block, g = gate, w = col in block)
__global__ void conv_w_kernel(const float* __restrict__ Wi, const float* __restrict__ Wf,
                              const float* __restrict__ Wc)
{
    const int j = blockIdx.x;
    const int b = j / 24, rem = j % 24;
    const int g = rem >> 3, w = rem & 7;
    const int n = b * 8 + w;
    const float* src_r = ((g == 0) ? Wi : (g == 1) ? Wf : Wc) + (size_t)n * KDIM;
    __half* dst = W16 + (size_t)j * KDIM;
#pragma unroll 1
    for (int f4 = threadIdx.x; f4 < KDIM / 4; f4 += 256) {
        int k = f4 * 4;
        float4 v = *(const float4*)(src_r + k);
        __half2 p0 = __floats2half2_rn(v.x, v.y);
        __half2 p1 = __floats2half2_rn(v.z, v.w);
        uint2 u;
        u.x = *(const uint32_t*)&p0;
        u.y = *(const uint32_t*)&p1;
        *(uint2*)(dst + k) = u;
    }
}

// ---- phase 2: GEMM + fused epilogue ------------------------------------------
// Per stage: A 128 rows x 64B, B 384 rows x 64B, row stride 80B.
__device__ __forceinline__ void issue_stage(uint32_t sbase, int tid, int kc, int m0, int rbase)
{
    const int k0 = kc * KC;
#pragma unroll
    for (int jj = 0; jj < 8; jj++) {
        int idx = tid + (jj << 8);
        if (idx < 512) {                        // A tile
            int row = idx >> 2, c = idx & 3;
            const __half* src = A16 + (size_t)(m0 + row) * KDIM + k0 + c * 8;
            cp16(sbase + (uint32_t)row * ROW_BYTES + (uint32_t)c * 16u, src);
        } else {                                // B tile
            int t = idx - 512;
            int row = t >> 2, c = t & 3;
            const __half* src = W16 + (size_t)(rbase + row) * KDIM + k0 + c * 8;
            cp16(sbase + A_TILE + (uint32_t)row * ROW_BYTES + (uint32_t)c * 16u, src);
        }
    }
    cp_commit();
}

__global__ void __launch_bounds__(256, 1) gazs_gemm_kernel(
    const float* __restrict__ h,
    const float* __restrict__ Wib, const float* __restrict__ Wfb,
    const float* __restrict__ Wcb, float* __restrict__ out)
{
    extern __shared__ __align__(128) char smem[];
    const uint32_t sb = smem_u32(smem);

    const int NC   = KDIM / KC;          // 128
    const int tid  = threadIdx.x;
    const int lane = tid & 31;
    const int wid  = tid >> 5;
    const int wn   = wid & 3;            // 4 n-groups (96 B-rows each)
    const int wm   = wid >> 2;           // 2 m-groups (64 rows each)
    const int m0   = blockIdx.y * BM;
    const int n0   = blockIdx.x * BN_GATE;
    const int rbase = blockIdx.x * BN;   // W16 row base (contiguous 384 rows)
    const int qr   = lane >> 2;
    const int qc   = lane & 3;

    // ldmatrix per-lane address offsets
    const uint32_t a_lb = (uint32_t)((wm * 64 + (lane & 15)) * ROW_BYTES + (lane >> 4) * 16);
    const uint32_t b_lb = (uint32_t)((wn * 96 + (lane & 7) + ((lane & 16) ? 8 : 0)) * ROW_BYTES
                                     + ((lane >> 3) & 1) * 16);

    float acc[4][12][4];
#pragma unroll
    for (int mt = 0; mt < 4; mt++)
#pragma unroll
        for (int nt = 0; nt < 12; nt++)
#pragma unroll
            for (int c = 0; c < 4; c++) acc[mt][nt][c] = 0.f;

    // prologue: 3 stages in flight
#pragma unroll
    for (int s = 0; s < NSTAGES - 1; s++)
        issue_stage(sb + (uint32_t)s * STAGE, tid, s, m0, rbase);

    for (int kc = 0; kc < NC; kc++) {
        int w = NC - 1 - kc; if (w > NSTAGES - 2) w = NSTAGES - 2;
        wait_groups(w);
        __syncthreads();

        int pf = kc + NSTAGES - 1;
        if (pf < NC)
            issue_stage(sb + (uint32_t)(pf & 3) * STAGE, tid, pf, m0, rbase);

        const uint32_t As = sb + (uint32_t)(kc & 3) * STAGE;
        const uint32_t Bs = As + A_TILE;

#pragma unroll
        for (int s = 0; s < 2; s++) {
            uint32_t a[4][4];
#pragma unroll
            for (int mt = 0; mt < 4; mt++)
                ldm_x4(a[mt], As + a_lb + (uint32_t)mt * (16 * ROW_BYTES) + (uint32_t)s * 32);
#pragma unroll
            for (int nb = 0; nb < 6; nb++) {
                uint32_t b[4];
                ldm_x4(b, Bs + b_lb + (uint32_t)nb * (16 * ROW_BYTES) + (uint32_t)s * 32);
#pragma unroll
                for (int mt = 0; mt < 4; mt++) {
                    mma_f16(acc[mt][2 * nb],     a[mt], b[0], b[1]);
                    mma_f16(acc[mt][2 * nb + 1], a[mt], b[2], b[3]);
                }
            }
        }
    }

    // ---- epilogue: in-register gate blend --------------------------------
    // acc[mt][bl*3+g]: rows m0+wm*64+mt*16+qr (+8); cols n0+(wn*4+bl)*8+qc*2 (+1)
#pragma unroll
    for (int mt = 0; mt < 4; mt++) {
        const int rb = m0 + wm * 64 + mt * 16 + qr;
#pragma unroll
        for (int bl = 0; bl < 4; bl++) {
            const int n = n0 + (wn * 4 + bl) * 8 + qc * 2;
            const float bi0 = __ldg(Wib + n), bi1 = __ldg(Wib + n + 1);
            const float bf0 = __ldg(Wfb + n), bf1 = __ldg(Wfb + n + 1);
            const float bc0 = __ldg(Wcb + n), bc1 = __ldg(Wcb + n + 1);
            const float* ai = acc[mt][bl * 3 + 0];
            const float* af = acc[mt][bl * 3 + 1];
            const float* ac = acc[mt][bl * 3 + 2];
#pragma unroll
            for (int rs = 0; rs < 2; rs++) {
                const int row = rb + rs * 8;
                const int i0 = rs * 2;
                float2 hv = *(const float2*)(h + (size_t)row * HDIM + n);

                float ig0 = fast_sigmoid(ai[i0] + bi0);
                float ig1 = fast_sigmoid(ai[i0 + 1] + bi1);
                float fg0 = fast_sigmoid(af[i0] + bf0);
                float fg1 = fast_sigmoid(af[i0 + 1] + bf1);
                float cg0 = fast_tanh(ac[i0] + bc0);
                float cg1 = fast_tanh(ac[i0 + 1] + bc1);
                float al0 = fast_sigmoid(ig0 - fg0);
                float al1 = fast_sigmoid(ig1 - fg1);

                float2 ov;
                ov.x = fmaf(al0, cg0 - hv.x, hv.x);
                ov.y = fmaf(al1, cg1 - hv.y, hv.y);
                *(float2*)(out + (size_t)row * HDIM + n) = ov;
            }
        }
    }
}

extern "C" void kernel_launch(void* const* d_in, const int* in_sizes, int n_in,
                              void* d_out, int out_size)
{
    const float* h   = (const float*)d_in[0];
    const float* x   = (const float*)d_in[1];
    const float* glo = (const float*)d_in[2];
    const float* Wi  = (const float*)d_in[3];
    const float* Wib = (const float*)d_in[4];
    const float* Wf  = (const float*)d_in[5];
    const float* Wfb = (const float*)d_in[6];
    const float* Wc  = (const float*)d_in[7];
    const float* Wcb = (const float*)d_in[8];
    float* out = (float*)d_out;

    cudaFuncSetAttribute(gazs_gemm_kernel,
                         cudaFuncAttributeMaxDynamicSharedMemorySize, DYN_SMEM);

    conv_a_kernel<<<BATCH, 256>>>(h, x, glo);
    conv_w_kernel<<<3 * HDIM, 256>>>(Wi, Wf, Wc);

    dim3 grid(HDIM / BN_GATE, BATCH / BM);   // (8, 64) = 512 CTAs
    gazs_gemm_kernel<<<grid, 256, DYN_SMEM>>>(h, Wib, Wfb, Wcb, out);
}

// round 4
// speedup vs baseline: 2.5124x; 1.0234x over previous
#include <cuda_runtime.h>
#include <cuda_fp16.h>
#include <cstdint>

// ---------------------------------------------------------------------------
// Gazs cell, legacy tensor-core path, fp16 in / fp32 accum.
// R4: 512-thread CTAs (4 warps/SMSP) for tensor-pipe saturation.
// CTA tile: 128 rows x 64 gate-cols (192 B-rows incl. 3 gates).
// Warp tile m32 x n48(B-rows); acc 48 floats/thread.
// ---------------------------------------------------------------------------

#define BM 128
#define BN_GATE 64
#define BN 192                     // 3 gates * 64 cols (B rows)
#define KC 32                      // fp16 k per stage (64B rows)
#define NSTAGES 4
#define ROW_BYTES 80               // 64B data + 16B pad
#define A_TILE (BM * ROW_BYTES)            // 10240
#define B_TILE (BN * ROW_BYTES)            // 15360
#define STAGE  (A_TILE + B_TILE)           // 25600
#define DYN_SMEM (NSTAGES * STAGE)         // 102400

#define BATCH 8192
#define HDIM  1024
#define KDIM  4096

__device__ __align__(16) __half A16[(size_t)BATCH * KDIM];
__device__ __align__(16) __half W16[(size_t)3 * HDIM * KDIM];

// ---- helpers ---------------------------------------------------------------
__device__ __forceinline__ uint32_t smem_u32(const void* p) {
    uint32_t a;
    asm("{ .reg .u64 t; cvta.to.shared.u64 t, %1; cvt.u32.u64 %0, t; }" : "=r"(a) : "l"(p));
    return a;
}
__device__ __forceinline__ void cp16(uint32_t dst, const void* src) {
    asm volatile("cp.async.cg.shared.global [%0], [%1], 16;" :: "r"(dst), "l"(src));
}
__device__ __forceinline__ void cp_commit() {
    asm volatile("cp.async.commit_group;" ::: "memory");
}
__device__ __forceinline__ void wait_groups(int w) {
    if (w == 0)      asm volatile("cp.async.wait_group 0;" ::: "memory");
    else if (w == 1) asm volatile("cp.async.wait_group 1;" ::: "memory");
    else             asm volatile("cp.async.wait_group 2;" ::: "memory");
}
__device__ __forceinline__ void ldm_x4(uint32_t r[4], uint32_t addr) {
    asm volatile("ldmatrix.sync.aligned.m8n8.x4.shared.b16 {%0,%1,%2,%3}, [%4];"
        : "=r"(r[0]), "=r"(r[1]), "=r"(r[2]), "=r"(r[3]) : "r"(addr));
}
__device__ __forceinline__ void mma_f16(float d[4], const uint32_t a[4],
                                        uint32_t b0, uint32_t b1) {
    asm volatile(
        "mma.sync.aligned.m16n8k16.row.col.f32.f16.f16.f32 "
        "{%0,%1,%2,%3},{%4,%5,%6,%7},{%8,%9},{%0,%1,%2,%3};"
        : "+f"(d[0]), "+f"(d[1]), "+f"(d[2]), "+f"(d[3])
        : "r"(a[0]), "r"(a[1]), "r"(a[2]), "r"(a[3]), "r"(b0), "r"(b1));
}
__device__ __forceinline__ float fast_sigmoid(float v) {
    return __fdividef(1.f, 1.f + __expf(-v));
}
__device__ __forceinline__ float fast_tanh(float v) {
    return 1.f - __fdividef(2.f, __expf(2.f * v) + 1.f);
}

// ---- phase 1: fused converter (A rows then W rows) --------------------------
// W16 row j, j = b*24 + g*8 + w  (b = n8 block, g = gate, w = col in block)
__global__ void conv_kernel(const float* __restrict__ h, const float* __restrict__ x,
                            const float* __restrict__ glo,
                            const float* __restrict__ Wi, const float* __restrict__ Wf,
                            const float* __restrict__ Wc)
{
    const int bid = blockIdx.x;
    if (bid < BATCH) {
        const int m = bid;
        __half* dst = A16 + (size_t)m * KDIM;
        const float* h_r = h + (size_t)m * HDIM;
        const float* x_r = x + (size_t)m * 2 * HDIM;
        const float* g_r = glo + (size_t)m * HDIM;
#pragma unroll 1
        for (int f4 = threadIdx.x; f4 < KDIM / 4; f4 += 256) {
            int k = f4 * 4;
            const float* src = (k < HDIM) ? (h_r + k)
                             : (k < 3 * HDIM) ? (x_r + (k - HDIM))
                             : (g_r + (k - 3 * HDIM));
            float4 v = *(const float4*)src;
            __half2 p0 = __floats2half2_rn(v.x, v.y);
            __half2 p1 = __floats2half2_rn(v.z, v.w);
            uint2 u;
            u.x = *(const uint32_t*)&p0;
            u.y = *(const uint32_t*)&p1;
            *(uint2*)(dst + k) = u;
        }
    } else {
        const int j = bid - BATCH;
        const int b = j / 24, rem = j % 24;
        const int g = rem >> 3, w = rem & 7;
        const int n = b * 8 + w;
        const float* src_r = ((g == 0) ? Wi : (g == 1) ? Wf : Wc) + (size_t)n * KDIM;
        __half* dst = W16 + (size_t)j * KDIM;
#pragma unroll 1
        for (int f4 = threadIdx.x; f4 < KDIM / 4; f4 += 256) {
            int k = f4 * 4;
            float4 v = *(const float4*)(src_r + k);
            __half2 p0 = __floats2half2_rn(v.x, v.y);
            __half2 p1 = __floats2half2_rn(v.z, v.w);
            uint2 u;
            u.x = *(const uint32_t*)&p0;
            u.y = *(const uint32_t*)&p1;
            *(uint2*)(dst + k) = u;
        }
    }
}

// ---- phase 2: GEMM + fused epilogue ------------------------------------------
// Per stage: A 128 rows x 64B, B 192 rows x 64B, row stride 80B; 1280 cp16.
__device__ __forceinline__ void issue_stage(uint32_t sbase, int tid, int kc, int m0, int rbase)
{
    const int k0 = kc * KC;
#pragma unroll
    for (int jj = 0; jj < 3; jj++) {
        int idx = tid + (jj << 9);
        if (idx < 512) {                        // A tile: 128 rows * 4
            int row = idx >> 2, c = idx & 3;
            const __half* src = A16 + (size_t)(m0 + row) * KDIM + k0 + c * 8;
            cp16(sbase + (uint32_t)row * ROW_BYTES + (uint32_t)c * 16u, src);
        } else if (idx < 1280) {                // B tile: 192 rows * 4
            int t = idx - 512;
            int row = t >> 2, c = t & 3;
            const __half* src = W16 + (size_t)(rbase + row) * KDIM + k0 + c * 8;
            cp16(sbase + A_TILE + (uint32_t)row * ROW_BYTES + (uint32_t)c * 16u, src);
        }
    }
    cp_commit();
}

__global__ void __launch_bounds__(512, 1) gazs_gemm_kernel(
    const float* __restrict__ h,
    const float* __restrict__ Wib, const float* __restrict__ Wfb,
    const float* __restrict__ Wcb, float* __restrict__ out)
{
    extern __shared__ __align__(128) char smem[];
    const uint32_t sb = smem_u32(smem);

    const int NC   = KDIM / KC;          // 128
    const int tid  = threadIdx.x;
    const int lane = tid & 31;
    const int wid  = tid >> 5;
    const int wn   = wid & 3;            // 4 n-groups, 48 B-rows each
    const int wm   = wid >> 2;           // 4 m-groups, 32 rows each
    const int m0   = blockIdx.y * BM;
    const int n0   = blockIdx.x * BN_GATE;
    const int rbase = blockIdx.x * BN;   // W16 row base
    const int qr   = lane >> 2;
    const int qc   = lane & 3;

    // ldmatrix per-lane base offsets
    const uint32_t a_lb = (uint32_t)((wm * 32 + (lane & 15)) * ROW_BYTES + (lane >> 4) * 16);
    const uint32_t b_lb = (uint32_t)((wn * 48 + (lane & 7) + ((lane & 16) ? 8 : 0)) * ROW_BYTES
                                     + ((lane >> 3) & 1) * 16);

    float acc[2][6][4];
#pragma unroll
    for (int mt = 0; mt < 2; mt++)
#pragma unroll
        for (int nt = 0; nt < 6; nt++)
#pragma unroll
            for (int c = 0; c < 4; c++) acc[mt][nt][c] = 0.f;

    // prologue: 3 stages in flight
#pragma unroll
    for (int s = 0; s < NSTAGES - 1; s++)
        issue_stage(sb + (uint32_t)s * STAGE, tid, s, m0, rbase);

    for (int kc = 0; kc < NC; kc++) {
        int w = NC - 1 - kc; if (w > NSTAGES - 2) w = NSTAGES - 2;
        wait_groups(w);
        __syncthreads();

        int pf = kc + NSTAGES - 1;
        if (pf < NC)
            issue_stage(sb + (uint32_t)(pf & 3) * STAGE, tid, pf, m0, rbase);

        const uint32_t As = sb + (uint32_t)(kc & 3) * STAGE;
        const uint32_t Bs = As + A_TILE;

#pragma unroll
        for (int s = 0; s < 2; s++) {
            uint32_t a[2][4], b[3][4];
#pragma unroll
            for (int mt = 0; mt < 2; mt++)
                ldm_x4(a[mt], As + a_lb + (uint32_t)mt * (16 * ROW_BYTES) + (uint32_t)s * 32);
#pragma unroll
            for (int nb = 0; nb < 3; nb++)
                ldm_x4(b[nb], Bs + b_lb + (uint32_t)nb * (16 * ROW_BYTES) + (uint32_t)s * 32);
#pragma unroll
            for (int nb = 0; nb < 3; nb++)
#pragma unroll
                for (int mt = 0; mt < 2; mt++) {
                    mma_f16(acc[mt][2 * nb],     a[mt], b[nb][0], b[nb][1]);
                    mma_f16(acc[mt][2 * nb + 1], a[mt], b[nb][2], b[nb][3]);
                }
        }
    }

    // ---- epilogue: in-register gate blend --------------------------------
    // acc[mt][bl*3+g]: rows m0+wm*32+mt*16+qr(+8); cols n0+(2*wn+bl)*8+qc*2(+1)
#pragma unroll
    for (int mt = 0; mt < 2; mt++) {
        const int rb = m0 + wm * 32 + mt * 16 + qr;
#pragma unroll
        for (int bl = 0; bl < 2; bl++) {
            const int n = n0 + (2 * wn + bl) * 8 + qc * 2;
            const float bi0 = __ldg(Wib + n), bi1 = __ldg(Wib + n + 1);
            const float bf0 = __ldg(Wfb + n), bf1 = __ldg(Wfb + n + 1);
            const float bc0 = __ldg(Wcb + n), bc1 = __ldg(Wcb + n + 1);
            const float* ai = acc[mt][bl * 3 + 0];
            const float* af = acc[mt][bl * 3 + 1];
            const float* ac = acc[mt][bl * 3 + 2];
#pragma unroll
            for (int rs = 0; rs < 2; rs++) {
                const int row = rb + rs * 8;
                const int i0 = rs * 2;
                float2 hv = *(const float2*)(h + (size_t)row * HDIM + n);

                float ig0 = fast_sigmoid(ai[i0] + bi0);
                float ig1 = fast_sigmoid(ai[i0 + 1] + bi1);
                float fg0 = fast_sigmoid(af[i0] + bf0);
                float fg1 = fast_sigmoid(af[i0 + 1] + bf1);
                float cg0 = fast_tanh(ac[i0] + bc0);
                float cg1 = fast_tanh(ac[i0 + 1] + bc1);
                float al0 = fast_sigmoid(ig0 - fg0);
                float al1 = fast_sigmoid(ig1 - fg1);

                float2 ov;
                ov.x = fmaf(al0, cg0 - hv.x, hv.x);
                ov.y = fmaf(al1, cg1 - hv.y, hv.y);
                *(float2*)(out + (size_t)row * HDIM + n) = ov;
            }
        }
    }
}

extern "C" void kernel_launch(void* const* d_in, const int* in_sizes, int n_in,
                              void* d_out, int out_size)
{
    const float* h   = (const float*)d_in[0];
    const float* x   = (const float*)d_in[1];
    const float* glo = (const float*)d_in[2];
    const float* Wi  = (const float*)d_in[3];
    const float* Wib = (const float*)d_in[4];
    const float* Wf  = (const float*)d_in[5];
    const float* Wfb = (const float*)d_in[6];
    const float* Wc  = (const float*)d_in[7];
    const float* Wcb = (const float*)d_in[8];
    float* out = (float*)d_out;

    cudaFuncSetAttribute(gazs_gemm_kernel,
                         cudaFuncAttributeMaxDynamicSharedMemorySize, DYN_SMEM);

    conv_kernel<<<BATCH + 3 * HDIM, 256>>>(h, x, glo, Wi, Wf, Wc);

    dim3 grid(HDIM / BN_GATE, BATCH / BM);   // (16, 64) = 1024 CTAs
    gazs_gemm_kernel<<<grid, 512, DYN_SMEM>>>(h, Wib, Wfb, Wcb, out);
}

// round 5
// speedup vs baseline: 2.5702x; 1.0230x over previous
#include <cuda_runtime.h>
#include <cuda_fp16.h>
#include <cstdint>

// ---------------------------------------------------------------------------
// Gazs cell, legacy tensor-core path, fp16 in / fp32 accum.
// R5: CTA tile 128 x 384 (3 gates x 128 cols), 16 warps = 4m x 4n,
// warp tile m32 x n96, acc 96 fp32/thread. B-fragment pipelining inside
// the MMA loop to overlap LDSM with HMMA issue.
// ---------------------------------------------------------------------------

#define BM 128
#define BN_GATE 128
#define BN 384                     // 3 gates * 128 cols (B rows)
#define KC 32                      // fp16 k per stage (64B rows)
#define NSTAGES 4
#define ROW_BYTES 80               // 64B data + 16B pad
#define A_TILE (BM * ROW_BYTES)            // 10240
#define B_TILE (BN * ROW_BYTES)            // 30720
#define STAGE  (A_TILE + B_TILE)           // 40960
#define DYN_SMEM (NSTAGES * STAGE)         // 163840

#define BATCH 8192
#define HDIM  1024
#define KDIM  4096

__device__ __align__(16) __half A16[(size_t)BATCH * KDIM];
__device__ __align__(16) __half W16[(size_t)3 * HDIM * KDIM];

// ---- helpers ---------------------------------------------------------------
__device__ __forceinline__ uint32_t smem_u32(const void* p) {
    uint32_t a;
    asm("{ .reg .u64 t; cvta.to.shared.u64 t, %1; cvt.u32.u64 %0, t; }" : "=r"(a) : "l"(p));
    return a;
}
__device__ __forceinline__ void cp16(uint32_t dst, const void* src) {
    asm volatile("cp.async.cg.shared.global [%0], [%1], 16;" :: "r"(dst), "l"(src));
}
__device__ __forceinline__ void cp_commit() {
    asm volatile("cp.async.commit_group;" ::: "memory");
}
__device__ __forceinline__ void wait_groups(int w) {
    if (w == 0)      asm volatile("cp.async.wait_group 0;" ::: "memory");
    else if (w == 1) asm volatile("cp.async.wait_group 1;" ::: "memory");
    else             asm volatile("cp.async.wait_group 2;" ::: "memory");
}
__device__ __forceinline__ void ldm_x4(uint32_t r[4], uint32_t addr) {
    asm volatile("ldmatrix.sync.aligned.m8n8.x4.shared.b16 {%0,%1,%2,%3}, [%4];"
        : "=r"(r[0]), "=r"(r[1]), "=r"(r[2]), "=r"(r[3]) : "r"(addr));
}
__device__ __forceinline__ void mma_f16(float d[4], const uint32_t a[4],
                                        uint32_t b0, uint32_t b1) {
    asm volatile(
        "mma.sync.aligned.m16n8k16.row.col.f32.f16.f16.f32 "
        "{%0,%1,%2,%3},{%4,%5,%6,%7},{%8,%9},{%0,%1,%2,%3};"
        : "+f"(d[0]), "+f"(d[1]), "+f"(d[2]), "+f"(d[3])
        : "r"(a[0]), "r"(a[1]), "r"(a[2]), "r"(a[3]), "r"(b0), "r"(b1));
}
__device__ __forceinline__ float fast_sigmoid(float v) {
    return __fdividef(1.f, 1.f + __expf(-v));
}
__device__ __forceinline__ float fast_tanh(float v) {
    return 1.f - __fdividef(2.f, __expf(2.f * v) + 1.f);
}

// ---- phase 1: fused converter (A rows then W rows) --------------------------
// W16 row j, j = b*24 + g*8 + w  (b = n8 block, g = gate, w = col in block)
__global__ void conv_kernel(const float* __restrict__ h, const float* __restrict__ x,
                            const float* __restrict__ glo,
                            const float* __restrict__ Wi, const float* __restrict__ Wf,
                            const float* __restrict__ Wc)
{
    const int bid = blockIdx.x;
    if (bid < BATCH) {
        const int m = bid;
        __half* dst = A16 + (size_t)m * KDIM;
        const float* h_r = h + (size_t)m * HDIM;
        const float* x_r = x + (size_t)m * 2 * HDIM;
        const float* g_r = glo + (size_t)m * HDIM;
#pragma unroll 1
        for (int f4 = threadIdx.x; f4 < KDIM / 4; f4 += 256) {
            int k = f4 * 4;
            const float* src = (k < HDIM) ? (h_r + k)
                             : (k < 3 * HDIM) ? (x_r + (k - HDIM))
                             : (g_r + (k - 3 * HDIM));
            float4 v = *(const float4*)src;
            __half2 p0 = __floats2half2_rn(v.x, v.y);
            __half2 p1 = __floats2half2_rn(v.z, v.w);
            uint2 u;
            u.x = *(const uint32_t*)&p0;
            u.y = *(const uint32_t*)&p1;
            *(uint2*)(dst + k) = u;
        }
    } else {
        const int j = bid - BATCH;
        const int b = j / 24, rem = j % 24;
        const int g = rem >> 3, w = rem & 7;
        const int n = b * 8 + w;
        const float* src_r = ((g == 0) ? Wi : (g == 1) ? Wf : Wc) + (size_t)n * KDIM;
        __half* dst = W16 + (size_t)j * KDIM;
#pragma unroll 1
        for (int f4 = threadIdx.x; f4 < KDIM / 4; f4 += 256) {
            int k = f4 * 4;
            float4 v = *(const float4*)(src_r + k);
            __half2 p0 = __floats2half2_rn(v.x, v.y);
            __half2 p1 = __floats2half2_rn(v.z, v.w);
            uint2 u;
            u.x = *(const uint32_t*)&p0;
            u.y = *(const uint32_t*)&p1;
            *(uint2*)(dst + k) = u;
        }
    }
}

// ---- phase 2: GEMM + fused epilogue ------------------------------------------
// Per stage: A 128 rows x 64B + B 384 rows x 64B, stride 80B; 2048 cp16.
__device__ __forceinline__ void issue_stage(uint32_t sbase, int tid, int kc, int m0, int rbase)
{
    const int k0 = kc * KC;
#pragma unroll
    for (int jj = 0; jj < 4; jj++) {
        int idx = tid + (jj << 9);
        if (idx < 512) {                        // A tile: 128 rows * 4
            int row = idx >> 2, c = idx & 3;
            const __half* src = A16 + (size_t)(m0 + row) * KDIM + k0 + c * 8;
            cp16(sbase + (uint32_t)row * ROW_BYTES + (uint32_t)c * 16u, src);
        } else {                                // B tile: 384 rows * 4
            int t = idx - 512;
            int row = t >> 2, c = t & 3;
            const __half* src = W16 + (size_t)(rbase + row) * KDIM + k0 + c * 8;
            cp16(sbase + A_TILE + (uint32_t)row * ROW_BYTES + (uint32_t)c * 16u, src);
        }
    }
    cp_commit();
}

__global__ void __launch_bounds__(512, 1) gazs_gemm_kernel(
    const float* __restrict__ h,
    const float* __restrict__ Wib, const float* __restrict__ Wfb,
    const float* __restrict__ Wcb, float* __restrict__ out)
{
    extern __shared__ __align__(128) char smem[];
    const uint32_t sb = smem_u32(smem);

    const int NC   = KDIM / KC;          // 128
    const int tid  = threadIdx.x;
    const int lane = tid & 31;
    const int wid  = tid >> 5;
    const int wn   = wid & 3;            // 4 n-groups, 96 B-rows each
    const int wm   = wid >> 2;           // 4 m-groups, 32 rows each
    const int m0   = blockIdx.y * BM;
    const int n0   = blockIdx.x * BN_GATE;
    const int rbase = blockIdx.x * BN;   // W16 row base
    const int qr   = lane >> 2;
    const int qc   = lane & 3;

    // ldmatrix per-lane base offsets
    const uint32_t a_lb = (uint32_t)((wm * 32 + (lane & 15)) * ROW_BYTES + (lane >> 4) * 16);
    const uint32_t b_lb = (uint32_t)((wn * 96 + (lane & 7) + ((lane & 16) ? 8 : 0)) * ROW_BYTES
                                     + ((lane >> 3) & 1) * 16);

    float acc[2][12][4];
#pragma unroll
    for (int mt = 0; mt < 2; mt++)
#pragma unroll
        for (int nt = 0; nt < 12; nt++)
#pragma unroll
            for (int c = 0; c < 4; c++) acc[mt][nt][c] = 0.f;

    // prologue: 3 stages in flight
#pragma unroll
    for (int s = 0; s < NSTAGES - 1; s++)
        issue_stage(sb + (uint32_t)s * STAGE, tid, s, m0, rbase);

    for (int kc = 0; kc < NC; kc++) {
        int w = NC - 1 - kc; if (w > NSTAGES - 2) w = NSTAGES - 2;
        wait_groups(w);
        __syncthreads();

        int pf = kc + NSTAGES - 1;
        if (pf < NC)
            issue_stage(sb + (uint32_t)(pf & 3) * STAGE, tid, pf, m0, rbase);

        const uint32_t As = sb + (uint32_t)(kc & 3) * STAGE;
        const uint32_t Bs = As + A_TILE;

#pragma unroll
        for (int s = 0; s < 2; s++) {
            uint32_t a0[4], a1[4];
            ldm_x4(a0, As + a_lb + (uint32_t)s * 32);
            ldm_x4(a1, As + a_lb + (uint32_t)(16 * ROW_BYTES) + (uint32_t)s * 32);

            // B-fragment pipelined loop: load nb+1 while MMAing nb
            uint32_t bcur[4], bnxt[4];
            ldm_x4(bcur, Bs + b_lb + (uint32_t)s * 32);
#pragma unroll
            for (int nb = 0; nb < 6; nb++) {
                if (nb < 5)
                    ldm_x4(bnxt, Bs + b_lb + (uint32_t)((nb + 1) * 16 * ROW_BYTES)
                                 + (uint32_t)s * 32);
                mma_f16(acc[0][2 * nb],     a0, bcur[0], bcur[1]);
                mma_f16(acc[0][2 * nb + 1], a0, bcur[2], bcur[3]);
                mma_f16(acc[1][2 * nb],     a1, bcur[0], bcur[1]);
                mma_f16(acc[1][2 * nb + 1], a1, bcur[2], bcur[3]);
#pragma unroll
                for (int q = 0; q < 4; q++) bcur[q] = bnxt[q];
            }
        }
    }

    // ---- epilogue: in-register gate blend --------------------------------
    // acc[mt][bl*3+g]: rows m0+wm*32+mt*16+qr(+8); cols n0+(wn*4+bl)*8+qc*2(+1)
#pragma unroll
    for (int mt = 0; mt < 2; mt++) {
        const int rb = m0 + wm * 32 + mt * 16 + qr;
#pragma unroll
        for (int bl = 0; bl < 4; bl++) {
            const int n = n0 + (wn * 4 + bl) * 8 + qc * 2;
            const float bi0 = __ldg(Wib + n), bi1 = __ldg(Wib + n + 1);
            const float bf0 = __ldg(Wfb + n), bf1 = __ldg(Wfb + n + 1);
            const float bc0 = __ldg(Wcb + n), bc1 = __ldg(Wcb + n + 1);
            const float* ai = acc[mt][bl * 3 + 0];
            const float* af = acc[mt][bl * 3 + 1];
            const float* ac = acc[mt][bl * 3 + 2];
#pragma unroll
            for (int rs = 0; rs < 2; rs++) {
                const int row = rb + rs * 8;
                const int i0 = rs * 2;
                float2 hv = *(const float2*)(h + (size_t)row * HDIM + n);

                float ig0 = fast_sigmoid(ai[i0] + bi0);
                float ig1 = fast_sigmoid(ai[i0 + 1] + bi1);
                float fg0 = fast_sigmoid(af[i0] + bf0);
                float fg1 = fast_sigmoid(af[i0 + 1] + bf1);
                float cg0 = fast_tanh(ac[i0] + bc0);
                float cg1 = fast_tanh(ac[i0 + 1] + bc1);
                float al0 = fast_sigmoid(ig0 - fg0);
                float al1 = fast_sigmoid(ig1 - fg1);

                float2 ov;
                ov.x = fmaf(al0, cg0 - hv.x, hv.x);
                ov.y = fmaf(al1, cg1 - hv.y, hv.y);
                *(float2*)(out + (size_t)row * HDIM + n) = ov;
            }
        }
    }
}

extern "C" void kernel_launch(void* const* d_in, const int* in_sizes, int n_in,
                              void* d_out, int out_size)
{
    const float* h   = (const float*)d_in[0];
    const float* x   = (const float*)d_in[1];
    const float* glo = (const float*)d_in[2];
    const float* Wi  = (const float*)d_in[3];
    const float* Wib = (const float*)d_in[4];
    const float* Wf  = (const float*)d_in[5];
    const float* Wfb = (const float*)d_in[6];
    const float* Wc  = (const float*)d_in[7];
    const float* Wcb = (const float*)d_in[8];
    float* out = (float*)d_out;

    cudaFuncSetAttribute(gazs_gemm_kernel,
                         cudaFuncAttributeMaxDynamicSharedMemorySize, DYN_SMEM);

    conv_kernel<<<BATCH + 3 * HDIM, 256>>>(h, x, glo, Wi, Wf, Wc);

    dim3 grid(HDIM / BN_GATE, BATCH / BM);   // (8, 64) = 512 CTAs
    gazs_gemm_kernel<<<grid, 512, DYN_SMEM>>>(h, Wib, Wfb, Wcb, out);
}